// round 2
// baseline (speedup 1.0000x reference)
#include <cuda_runtime.h>
#include <stdint.h>

#define IN_F   4096
#define OUT_F  4096
#define RANK_  16
#define MROWS  16384            // 4*4096 flattened rows
#define TH_    0xE6666600u      // bits < TH_  <=>  uniform(bits) < 0.9f (exact)

// scratch (allocation-free rule: __device__ globals)
static __device__ float g_At[IN_F * RANK_];   // [k][r]  = A[r][k]
static __device__ float g_Bt[RANK_ * OUT_F];  // [r][o]  = B[o][r]
static __device__ float g_T [MROWS * RANK_];  // t = x @ A^T

// ---------- f32x2 helpers (packed fp32 pair in one 64-bit reg) ----------
__device__ __forceinline__ unsigned long long pack2f(float lo, float hi) {
    unsigned long long r;
    asm("mov.b64 %0, {%1, %2};" : "=l"(r)
        : "r"(__float_as_uint(lo)), "r"(__float_as_uint(hi)));
    return r;
}
__device__ __forceinline__ void unpack2f(unsigned long long v, float& lo, float& hi) {
    unsigned a, b;
    asm("mov.b64 {%0, %1}, %2;" : "=r"(a), "=r"(b) : "l"(v));
    lo = __uint_as_float(a); hi = __uint_as_float(b);
}
__device__ __forceinline__ unsigned long long ffma2(unsigned long long a,
                                                    unsigned long long b,
                                                    unsigned long long c) {
    unsigned long long d;
    asm("fma.rn.f32x2 %0, %1, %2, %3;" : "=l"(d) : "l"(a), "l"(b), "l"(c));
    return d;
}
__device__ __forceinline__ unsigned long long fadd2(unsigned long long a,
                                                    unsigned long long b) {
    unsigned long long d;
    asm("add.rn.f32x2 %0, %1, %2;" : "=l"(d) : "l"(a), "l"(b));
    return d;
}

// ---------- partitionable-threefry bits for flat index i ----------
// JAX (jax_threefry_partitionable=True, default in modern JAX):
//   counter = 64-bit iota -> (hi, lo) = (0, i) for N < 2^32
//   (o0, o1) = threefry2x32(key=(0,42), (0, i));  bits32 = o0 ^ o1
__device__ __forceinline__ unsigned tf_bits(unsigned i) {
    const unsigned ks1 = 42u, ks2 = 0x1BD11BF0u;  // 0x1BD11BDA ^ 0 ^ 42
    unsigned x0 = 0u;          // counter_hi(0) + ks0(0)
    unsigned x1 = i + ks1;     // counter_lo + ks1
#define TF_RND(R) { x0 += x1; x1 = __funnelshift_l(x1, x1, (R)); x1 ^= x0; }
    TF_RND(13) TF_RND(15) TF_RND(26) TF_RND(6)
    x0 += ks1;              x1 += ks2 + 1u;
    TF_RND(17) TF_RND(29) TF_RND(16) TF_RND(24)
    x0 += ks2;              x1 += 2u;              // ks0 + 2
    TF_RND(13) TF_RND(15) TF_RND(26) TF_RND(6)
    /* x0 += ks0(=0) */     x1 += ks1 + 3u;
    TF_RND(17) TF_RND(29) TF_RND(16) TF_RND(24)
    x0 += ks1;              x1 += ks2 + 4u;
    TF_RND(13) TF_RND(15) TF_RND(26) TF_RND(6)
    x0 += ks2;              x1 += 5u;              // ks0 + 5
#undef TF_RND
    return x0 ^ x1;
}

// ---------- k0: transpose A -> At, B -> Bt (tiny, one-shot) ----------
__global__ void k0_transpose(const float* __restrict__ A, const float* __restrict__ B) {
    int idx = blockIdx.x * blockDim.x + threadIdx.x;   // 0..4095
    if (idx < IN_F) {
#pragma unroll
        for (int r = 0; r < RANK_; ++r)
            g_At[idx * RANK_ + r] = A[r * IN_F + idx];
    }
    if (idx < OUT_F) {
#pragma unroll
        for (int r = 0; r < RANK_; ++r)
            g_Bt[r * OUT_F + idx] = B[idx * RANK_ + r];
    }
}

// ---------- k1: T = x @ A^T, smem-tiled, f32x2 over r-pairs ----------
#define BM 32     // rows per block
#define KC 128    // k-chunk

__global__ void __launch_bounds__(128, 2) k1_xa(const float* __restrict__ x) {
    __shared__ float              x_s[BM][KC];            // 16 KB
    __shared__ unsigned long long At_s2[RANK_ / 2][KC];   // 8 KB, (r even, r odd) pairs

    const int tid  = threadIdx.x;
    const int wid  = tid >> 5;   // m-group 0..3 (8 rows each)
    const int lane = tid & 31;
    const int m0   = blockIdx.x * BM;

    unsigned long long acc2[8][8];
#pragma unroll
    for (int mi = 0; mi < 8; ++mi)
#pragma unroll
        for (int rr = 0; rr < 8; ++rr) acc2[mi][rr] = 0ull;

    for (int c = 0; c < IN_F / KC; ++c) {
        // load x tile (32x128 floats) via float4, fully coalesced
        const float4* xg = reinterpret_cast<const float4*>(x + (size_t)m0 * IN_F + c * KC);
#pragma unroll
        for (int i = 0; i < 8; ++i) {
            int idx4 = tid + 128 * i;          // 0..1023
            int row  = idx4 >> 5;              // 32 float4 per row
            int col4 = idx4 & 31;
            float4 v = xg[(size_t)row * (IN_F / 4) + col4];
            *reinterpret_cast<float4*>(&x_s[row][col4 * 4]) = v;
        }
        // load At chunk: one k-row (16 floats) per thread, pack r-pairs
        {
            int kk = tid;  // 0..127
            const float4* ag = reinterpret_cast<const float4*>(g_At + (size_t)(c * KC + kk) * RANK_);
            float4 a0 = ag[0], a1 = ag[1], a2v = ag[2], a3 = ag[3];
            At_s2[0][kk] = pack2f(a0.x,  a0.y);
            At_s2[1][kk] = pack2f(a0.z,  a0.w);
            At_s2[2][kk] = pack2f(a1.x,  a1.y);
            At_s2[3][kk] = pack2f(a1.z,  a1.w);
            At_s2[4][kk] = pack2f(a2v.x, a2v.y);
            At_s2[5][kk] = pack2f(a2v.z, a2v.w);
            At_s2[6][kk] = pack2f(a3.x,  a3.y);
            At_s2[7][kk] = pack2f(a3.z,  a3.w);
        }
        __syncthreads();

#pragma unroll 1
        for (int s = 0; s < KC / 32; ++s) {
            int k = lane + 32 * s;
            unsigned long long a2[8];
#pragma unroll
            for (int rr = 0; rr < 8; ++rr) a2[rr] = At_s2[rr][k];
#pragma unroll
            for (int mi = 0; mi < 8; ++mi) {
                float xv = x_s[wid * 8 + mi][k];
                unsigned long long xx = pack2f(xv, xv);
#pragma unroll
                for (int rr = 0; rr < 8; ++rr)
                    acc2[mi][rr] = ffma2(xx, a2[rr], acc2[mi][rr]);
            }
        }
        __syncthreads();
    }

    // butterfly reduce across the 32 k-lanes
#pragma unroll
    for (int off = 16; off > 0; off >>= 1) {
#pragma unroll
        for (int mi = 0; mi < 8; ++mi)
#pragma unroll
            for (int rr = 0; rr < 8; ++rr) {
                unsigned long long o = __shfl_xor_sync(0xffffffffu, acc2[mi][rr], off);
                acc2[mi][rr] = fadd2(acc2[mi][rr], o);
            }
    }
    if (lane < RANK_) {
        int r = lane;
#pragma unroll
        for (int mi = 0; mi < 8; ++mi) {
            float lo, hi;
            unpack2f(acc2[mi][r >> 1], lo, hi);
            g_T[(size_t)(m0 + wid * 8 + mi) * RANK_ + r] = (r & 1) ? hi : lo;
        }
    }
}

// ---------- k2: y = dropout( (T @ B^T) * scaling ), partitionable threefry ----------
#define K2ROWS 8

__global__ void __launch_bounds__(256) k2_by(float* __restrict__ y) {
    const float CMUL = 2.0f / 0.9f;   // scaling / keep
    __shared__ unsigned long long T_s2[K2ROWS][RANK_];  // (t,t) packed

    const int tid   = threadIdx.x;
    const int rbase = blockIdx.x * K2ROWS;

    if (tid < K2ROWS * RANK_) {
        int row_in = tid >> 4;          // 0..7
        int r      = tid & 15;
        float v = g_T[(size_t)(rbase + row_in) * RANK_ + r];
        T_s2[row_in][r] = pack2f(v, v);
    }
    __syncthreads();

#pragma unroll 1
    for (int j = 0; j < 4; ++j) {
        int oq    = tid + 256 * j;      // o-quad 0..1023
        int obase = oq * 4;

        unsigned long long accL[K2ROWS], accH[K2ROWS];
#pragma unroll
        for (int q = 0; q < K2ROWS; ++q) { accL[q] = 0ull; accH[q] = 0ull; }

#pragma unroll
        for (int r = 0; r < RANK_; ++r) {
            float4 b4 = *reinterpret_cast<const float4*>(&g_Bt[r * OUT_F + obase]);
            unsigned long long bL = pack2f(b4.x, b4.y);
            unsigned long long bH = pack2f(b4.z, b4.w);
#pragma unroll
            for (int q = 0; q < K2ROWS; ++q) {
                unsigned long long t2 = T_s2[q][r];
                accL[q] = ffma2(t2, bL, accL[q]);
                accH[q] = ffma2(t2, bH, accH[q]);
            }
        }

#pragma unroll
        for (int q = 0; q < K2ROWS; ++q) {
            int m = rbase + q;
            unsigned base_i = (unsigned)m * 4096u + (unsigned)obase;
            float v[4];
            unpack2f(accL[q], v[0], v[1]);
            unpack2f(accH[q], v[2], v[3]);
            float o[4];
#pragma unroll
            for (int e = 0; e < 4; ++e) {
                unsigned bits = tf_bits(base_i + e);
                o[e] = (bits < TH_) ? v[e] * CMUL : 0.0f;
            }
            *reinterpret_cast<float4*>(&y[(size_t)m * 4096 + obase]) =
                make_float4(o[0], o[1], o[2], o[3]);
        }
    }
}

extern "C" void kernel_launch(void* const* d_in, const int* in_sizes, int n_in,
                              void* d_out, int out_size) {
    const float* x = (const float*)d_in[0];
    const float* A = (const float*)d_in[1];
    const float* B = (const float*)d_in[2];
    float*       y = (float*)d_out;

    k0_transpose<<<16, 256>>>(A, B);
    k1_xa<<<MROWS / BM, 128>>>(x);
    k2_by<<<MROWS / K2ROWS, 256>>>(y);
}

// round 3
// speedup vs baseline: 1.0271x; 1.0271x over previous
#include <cuda_runtime.h>
#include <stdint.h>

#define IN_F   4096
#define OUT_F  4096
#define RANK_  16
#define MROWS  16384            // 4*4096 flattened rows
#define TH_    0xE6666600u      // bits < TH_  <=>  uniform(bits) < 0.9f (exact)

// scratch (allocation-free rule: __device__ globals)
static __device__ float g_At[IN_F * RANK_];   // [k][r]  = A[r][k]
static __device__ float g_Bt[RANK_ * OUT_F];  // [r][o]  = B[o][r] * (scaling/keep)
static __device__ float g_T [MROWS * RANK_];  // t = x @ A^T

// ---------- f32x2 helpers (packed fp32 pair in one 64-bit reg) ----------
__device__ __forceinline__ unsigned long long pack2f(float lo, float hi) {
    unsigned long long r;
    asm("mov.b64 %0, {%1, %2};" : "=l"(r)
        : "r"(__float_as_uint(lo)), "r"(__float_as_uint(hi)));
    return r;
}
__device__ __forceinline__ void unpack2f(unsigned long long v, float& lo, float& hi) {
    unsigned a, b;
    asm("mov.b64 {%0, %1}, %2;" : "=r"(a), "=r"(b) : "l"(v));
    lo = __uint_as_float(a); hi = __uint_as_float(b);
}
__device__ __forceinline__ unsigned long long ffma2(unsigned long long a,
                                                    unsigned long long b,
                                                    unsigned long long c) {
    unsigned long long d;
    asm("fma.rn.f32x2 %0, %1, %2, %3;" : "=l"(d) : "l"(a), "l"(b), "l"(c));
    return d;
}
__device__ __forceinline__ unsigned long long fadd2(unsigned long long a,
                                                    unsigned long long b) {
    unsigned long long d;
    asm("add.rn.f32x2 %0, %1, %2;" : "=l"(d) : "l"(a), "l"(b));
    return d;
}

// ---------- partitionable-threefry bits for flat index i ----------
// JAX (jax_threefry_partitionable=True): counter (0, i), key (0, 42),
// bits32 = o0 ^ o1 of a single threefry2x32-20.
__device__ __forceinline__ unsigned tf_bits(unsigned i) {
    const unsigned ks1 = 42u, ks2 = 0x1BD11BF0u;  // 0x1BD11BDA ^ 0 ^ 42
    unsigned x0 = 0u;          // counter_hi(0) + ks0(0)
    unsigned x1 = i + ks1;     // counter_lo + ks1
#define TF_RND(R) { x0 += x1; x1 = __funnelshift_l(x1, x1, (R)); x1 ^= x0; }
    TF_RND(13) TF_RND(15) TF_RND(26) TF_RND(6)
    x0 += ks1;              x1 += ks2 + 1u;
    TF_RND(17) TF_RND(29) TF_RND(16) TF_RND(24)
    x0 += ks2;              x1 += 2u;              // ks0 + 2
    TF_RND(13) TF_RND(15) TF_RND(26) TF_RND(6)
    /* x0 += ks0(=0) */     x1 += ks1 + 3u;
    TF_RND(17) TF_RND(29) TF_RND(16) TF_RND(24)
    x0 += ks1;              x1 += ks2 + 4u;
    TF_RND(13) TF_RND(15) TF_RND(26) TF_RND(6)
    x0 += ks2;              x1 += 5u;              // ks0 + 5
#undef TF_RND
    return x0 ^ x1;
}

// ---------- k0: transpose A -> At, B*(2/0.9) -> Bt ----------
__global__ void k0_transpose(const float* __restrict__ A, const float* __restrict__ B) {
    const float CMUL = 2.0f / 0.9f;   // scaling / keep, folded into Bt
    int idx = blockIdx.x * blockDim.x + threadIdx.x;   // 0..4095
    if (idx < IN_F) {
#pragma unroll
        for (int r = 0; r < RANK_; ++r)
            g_At[idx * RANK_ + r] = A[r * IN_F + idx];
    }
    if (idx < OUT_F) {
#pragma unroll
        for (int r = 0; r < RANK_; ++r)
            g_Bt[r * OUT_F + idx] = B[idx * RANK_ + r] * CMUL;
    }
}

// ---------- k1: T = x @ A^T, smem-tiled, f32x2 over r-pairs ----------
#define BM 32     // rows per block
#define KC 128    // k-chunk

__global__ void __launch_bounds__(128, 2) k1_xa(const float* __restrict__ x) {
    __shared__ float              x_s[BM][KC];            // 16 KB
    __shared__ unsigned long long At_s2[RANK_ / 2][KC];   // 8 KB, (r even, r odd) pairs

    const int tid  = threadIdx.x;
    const int wid  = tid >> 5;   // m-group 0..3 (8 rows each)
    const int lane = tid & 31;
    const int m0   = blockIdx.x * BM;

    unsigned long long acc2[8][8];
#pragma unroll
    for (int mi = 0; mi < 8; ++mi)
#pragma unroll
        for (int rr = 0; rr < 8; ++rr) acc2[mi][rr] = 0ull;

    for (int c = 0; c < IN_F / KC; ++c) {
        const float4* xg = reinterpret_cast<const float4*>(x + (size_t)m0 * IN_F + c * KC);
#pragma unroll
        for (int i = 0; i < 8; ++i) {
            int idx4 = tid + 128 * i;          // 0..1023
            int row  = idx4 >> 5;              // 32 float4 per row
            int col4 = idx4 & 31;
            float4 v = xg[(size_t)row * (IN_F / 4) + col4];
            *reinterpret_cast<float4*>(&x_s[row][col4 * 4]) = v;
        }
        {
            int kk = tid;  // 0..127
            const float4* ag = reinterpret_cast<const float4*>(g_At + (size_t)(c * KC + kk) * RANK_);
            float4 a0 = ag[0], a1 = ag[1], a2v = ag[2], a3 = ag[3];
            At_s2[0][kk] = pack2f(a0.x,  a0.y);
            At_s2[1][kk] = pack2f(a0.z,  a0.w);
            At_s2[2][kk] = pack2f(a1.x,  a1.y);
            At_s2[3][kk] = pack2f(a1.z,  a1.w);
            At_s2[4][kk] = pack2f(a2v.x, a2v.y);
            At_s2[5][kk] = pack2f(a2v.z, a2v.w);
            At_s2[6][kk] = pack2f(a3.x,  a3.y);
            At_s2[7][kk] = pack2f(a3.z,  a3.w);
        }
        __syncthreads();

#pragma unroll 1
        for (int s = 0; s < KC / 32; ++s) {
            int k = lane + 32 * s;
            unsigned long long a2[8];
#pragma unroll
            for (int rr = 0; rr < 8; ++rr) a2[rr] = At_s2[rr][k];
#pragma unroll
            for (int mi = 0; mi < 8; ++mi) {
                float xv = x_s[wid * 8 + mi][k];
                unsigned long long xx = pack2f(xv, xv);
#pragma unroll
                for (int rr = 0; rr < 8; ++rr)
                    acc2[mi][rr] = ffma2(xx, a2[rr], acc2[mi][rr]);
            }
        }
        __syncthreads();
    }

#pragma unroll
    for (int off = 16; off > 0; off >>= 1) {
#pragma unroll
        for (int mi = 0; mi < 8; ++mi)
#pragma unroll
            for (int rr = 0; rr < 8; ++rr) {
                unsigned long long o = __shfl_xor_sync(0xffffffffu, acc2[mi][rr], off);
                acc2[mi][rr] = fadd2(acc2[mi][rr], o);
            }
    }
    if (lane < RANK_) {
        int r = lane;
#pragma unroll
        for (int mi = 0; mi < 8; ++mi) {
            float lo, hi;
            unpack2f(acc2[mi][r >> 1], lo, hi);
            g_T[(size_t)(m0 + wid * 8 + mi) * RANK_ + r] = (r & 1) ? hi : lo;
        }
    }
}

// ---------- k2: y = dropout( T @ Bt ), Bt tile staged in smem ----------
// tile: 16 rows x 512 cols per block; 256 threads, 2 cols (1 f32x2 pair) each.
#define RB 16
#define CBT 512

__global__ void __launch_bounds__(256) k2_by(float* __restrict__ y) {
    __shared__ unsigned long long B_s[RANK_][CBT / 2];  // 32 KB, col pairs
    __shared__ unsigned long long T_s[RB][RANK_];       // 2 KB, (t,t) packed

    const int tid   = threadIdx.x;
    const int cb    = (blockIdx.x & 7) * CBT;           // col tile 0..7
    const int rbase = (blockIdx.x >> 3) * RB;           // row tile

    // load Bt slice: 16 x 512 floats, coalesced float4
#pragma unroll
    for (int i = 0; i < 8; ++i) {
        int idx4 = tid + 256 * i;          // 0..2047 float4s
        int r    = idx4 >> 7;              // 128 float4 per row
        int c4   = idx4 & 127;
        float4 v = *reinterpret_cast<const float4*>(&g_Bt[r * OUT_F + cb + c4 * 4]);
        B_s[r][c4 * 2]     = pack2f(v.x, v.y);
        B_s[r][c4 * 2 + 1] = pack2f(v.z, v.w);
    }
    // load T rows for this block (256 values)
    {
        int row = tid >> 4;                // 0..15
        int r   = tid & 15;
        float v = g_T[(size_t)(rbase + row) * RANK_ + r];
        T_s[row][r] = pack2f(v, v);
    }
    __syncthreads();

    // hold this thread's B column-pair across all rows: b[r], r = 0..15
    unsigned long long b[RANK_];
#pragma unroll
    for (int r = 0; r < RANK_; ++r) b[r] = B_s[r][tid];

#pragma unroll 1
    for (int q = 0; q < RB; ++q) {
        unsigned long long acc = 0ull;
#pragma unroll
        for (int rp = 0; rp < RANK_ / 2; ++rp) {
            // LDS.128: t2 pair for (2rp, 2rp+1), broadcast across warp
            ulonglong2 t2 = *reinterpret_cast<const ulonglong2*>(&T_s[q][rp * 2]);
            acc = ffma2(t2.x, b[rp * 2],     acc);
            acc = ffma2(t2.y, b[rp * 2 + 1], acc);
        }
        float v0, v1;
        unpack2f(acc, v0, v1);

        int m = rbase + q;
        unsigned base_i = (unsigned)m * 4096u + (unsigned)(cb + tid * 2);
        unsigned bits0 = tf_bits(base_i);
        unsigned bits1 = tf_bits(base_i + 1u);
        float o0 = (bits0 < TH_) ? v0 : 0.0f;
        float o1 = (bits1 < TH_) ? v1 : 0.0f;
        *reinterpret_cast<float2*>(&y[(size_t)m * 4096 + cb + tid * 2]) =
            make_float2(o0, o1);
    }
}

extern "C" void kernel_launch(void* const* d_in, const int* in_sizes, int n_in,
                              void* d_out, int out_size) {
    const float* x = (const float*)d_in[0];
    const float* A = (const float*)d_in[1];
    const float* B = (const float*)d_in[2];
    float*       y = (float*)d_out;

    k0_transpose<<<16, 256>>>(A, B);
    k1_xa<<<MROWS / BM, 128>>>(x);
    k2_by<<<(MROWS / RB) * (OUT_F / CBT), 256>>>(y);
}